// round 4
// baseline (speedup 1.0000x reference)
#include <cuda_runtime.h>
#include <cuda_fp16.h>

#define BB 16
#define CC 3
#define HH 256
#define WW 256
#define MM 100
#define HW (HH * WW)

// Padded, pair-overlapped, channel-packed fp16 image.
// Row index ry in [0,260) holds image row (ry-2)  (zeros when OOB).
// Entry index ex in [0,259) holds pixel pair (ex-2, ex-1) (zeros when OOB).
// Entry = uint4: (half2(c0,c1) lo, half2(c2,0) lo, half2(c0,c1) hi, half2(c2,0) hi).
// Clamping x0 to [-2,256] / y0 to [-2,256] lands every fully-OOB tap on
// all-zero entries, so no validity selects are needed in the hot loop.
#define PROWS 260
#define PSTR 272   // row stride in entries (slack never read)
__device__ uint4 g_packed[BB * PROWS * PSTR];

__device__ __forceinline__ unsigned packh2(float a, float b) {
    __half2 h = __halves2half2(__float2half(a), __float2half(b));
    return *reinterpret_cast<unsigned*>(&h);
}

__global__ void pack_kernel(const float* __restrict__ x) {
    int ex = blockIdx.x * blockDim.x + threadIdx.x;   // entry index
    if (ex >= 259) return;
    int ry = blockIdx.y;                              // padded row
    int b = blockIdx.z;
    int px = ex - 2;                                  // lo pixel x
    int py = ry - 2;                                  // image row
    float v0l = 0.f, v1l = 0.f, v2l = 0.f, v0h = 0.f, v1h = 0.f, v2h = 0.f;
    if ((unsigned)py < (unsigned)HH) {
        const float* xb = x + (size_t)b * CC * HW + py * WW;
        if ((unsigned)px < (unsigned)WW) {
            v0l = xb[px]; v1l = xb[px + HW]; v2l = xb[px + 2 * HW];
        }
        int ph = px + 1;
        if ((unsigned)ph < (unsigned)WW) {
            v0h = xb[ph]; v1h = xb[ph + HW]; v2h = xb[ph + 2 * HW];
        }
    }
    uint4 e;
    e.x = packh2(v0l, v1l);
    e.y = packh2(v2l, 0.f);
    e.z = packh2(v0h, v1h);
    e.w = packh2(v2h, 0.f);
    g_packed[(b * PROWS + ry) * PSTR + ex] = e;
}

__device__ __forceinline__ void accum(unsigned c01, unsigned c2w, float w,
                                      float& a0, float& a1, float& a2) {
    __half2 h01 = *reinterpret_cast<const __half2*>(&c01);
    float2 f01 = __half22float2(h01);
    float f2 = __half2float(reinterpret_cast<const __half*>(&c2w)[0]);
    a0 = fmaf(w, f01.x, a0);
    a1 = fmaf(w, f01.y, a1);
    a2 = fmaf(w, f2, a2);
}

// Warp = 4x4 output tile x 2 ky-halves (lane pairs). Block = 8x8 tile.
__global__ void __launch_bounds__(128) stn_kernel(const float* __restrict__ theta,
                                                  float* __restrict__ out) {
    int tid = threadIdx.x;
    int half = tid & 1;
    int p = (tid >> 1) & 15;
    int w = tid >> 5;
    int i = blockIdx.y * 8 + ((w >> 1) << 2) + (p >> 2);
    int j = blockIdx.x * 8 + ((w & 1) << 2) + (p & 3);
    int b = blockIdx.z;
    bool valid = (i < MM) && (j < MM);
    i = min(i, MM - 1);
    j = min(j, MM - 1);

    const float* th = theta + b * 6;
    float t00 = __ldg(th + 0), t01 = __ldg(th + 1), t02 = __ldg(th + 2);
    float t10 = __ldg(th + 3), t11 = __ldg(th + 4), t12 = __ldg(th + 5);

    float lx = (j + 0.5f) * (2.0f / MM) - 1.0f;
    float ly = (i + 0.5f) * (2.0f / MM) - 1.0f;
    float gx = fmaf(t00, lx, fmaf(t01, ly, t02));
    float gy = fmaf(t10, lx, fmaf(t11, ly, t12));

    float ixb = fmaf(gx, 0.5f * WW, 0.5f * WW - 0.5f);
    float iyb = fmaf(gy, 0.5f * HH, 0.5f * HH - 0.5f);

    const float cstep = (0.5f * WW) / (6.0f * 99.0f);
    float ux = t00 * cstep, uy = t10 * cstep;
    float vx = t01 * cstep, vy = t11 * cstep;

    float wk[11];
    float wsum = 0.0f;
#pragma unroll
    for (int k = 0; k < 11; k++) {
        float d = (float)(k - 5) * (1.0f / 6.0f);
        wk[k] = expf(-8.0f * d * d);
        wsum += wk[k];
    }
    float inv = 1.0f / (wsum * wsum);

    const uint4* __restrict__ base = g_packed + b * (PROWS * PSTR);

    float acc0 = 0.0f, acc1 = 0.0f, acc2 = 0.0f;

#pragma unroll 1
    for (int ky = half; ky < 11; ky += 2) {
        float dky = (float)(ky - 5);
        float dd = dky * (1.0f / 6.0f);
        float wyk = expf(-8.0f * dd * dd);
        float ixr = fmaf(dky, vx, ixb);
        float iyr = fmaf(dky, vy, iyb);
#pragma unroll
        for (int kx = 0; kx < 11; kx++) {
            float dkx = (float)(kx - 5);
            float ix = fmaf(dkx, ux, ixr);
            float iy = fmaf(dkx, uy, iyr);

            float x0f = floorf(ix);
            float y0f = floorf(iy);
            float fx = ix - x0f;
            float fy = iy - y0f;
            int x0 = (int)x0f;
            int y0 = (int)y0f;

            // clamp into padded index space; OOB taps hit all-zero entries
            int xc = min(max(x0, -2), WW);
            int yc = min(max(y0, -2), HH);

            int idx = (yc + 2) * PSTR + (xc + 2);
            uint4 q0 = base[idx];          // pixels (xc, xc+1) at row yc
            uint4 q1 = base[idx + PSTR];   // pixels (xc, xc+1) at row yc+1

            float wgt = wyk * wk[kx];
            float gx0 = 1.0f - fx;
            float a0 = wgt * (1.0f - fy);
            float a1 = wgt * fy;
            float w00 = a0 * gx0, w01 = a0 * fx;
            float w10 = a1 * gx0, w11 = a1 * fx;

            accum(q0.x, q0.y, w00, acc0, acc1, acc2);
            accum(q0.z, q0.w, w01, acc0, acc1, acc2);
            accum(q1.x, q1.y, w10, acc0, acc1, acc2);
            accum(q1.z, q1.w, w11, acc0, acc1, acc2);
        }
    }

    acc0 += __shfl_xor_sync(0xffffffff, acc0, 1);
    acc1 += __shfl_xor_sync(0xffffffff, acc1, 1);
    acc2 += __shfl_xor_sync(0xffffffff, acc2, 1);

    if (half == 0 && valid) {
        int r = i * MM + j;
        float* ob = out + b * (CC * MM * MM) + r;
        ob[0]           = acc0 * inv;
        ob[MM * MM]     = acc1 * inv;
        ob[2 * MM * MM] = acc2 * inv;
    }
}

extern "C" void kernel_launch(void* const* d_in, const int* in_sizes, int n_in,
                              void* d_out, int out_size) {
    const float* x = (const float*)d_in[0];
    const float* th = (const float*)d_in[1];
    if (n_in >= 2 && in_sizes[0] == 96) {
        x = (const float*)d_in[1];
        th = (const float*)d_in[0];
    }
    float* out = (float*)d_out;

    {
        dim3 grid(3, PROWS, BB);   // 3*128 = 384 >= 259 entries
        pack_kernel<<<grid, 128>>>(x);
    }
    {
        dim3 grid(13, 13, BB);     // 13*8 >= 100
        stn_kernel<<<grid, 128>>>(th, out);
    }
    (void)out_size;
}

// round 5
// speedup vs baseline: 1.0547x; 1.0547x over previous
#include <cuda_runtime.h>
#include <cuda_fp16.h>

#define BB 16
#define CC 3
#define HH 256
#define WW 256
#define MM 100
#define HW (HH * WW)

// Quad-packed fp16 image, zero-halo padded, two planes.
// Entry (ey, ex) represents bilinear cell (x0, y0) = (ex-2, ey-2):
//   c01 plane (uint4): half2(c0,c1) at corners (y0,x0),(y0,x0+1),(y0+1,x0),(y0+1,x0+1)
//   c2  plane (uint2): half2(c2@(y0,x0), c2@(y0,x0+1)), half2(c2@(y0+1,x0), c2@(y0+1,x0+1))
// Clamping the biased cell index to [0,258] lands every fully-OOB tap on all-zero
// entries, so the hot loop has no validity selects at all.
#define NE 259          // entries per row (x0 in [-2,256])
#define NR 259          // entry rows      (y0 in [-2,256])
#define STR01 264       // c01 row stride (264*16B = 33 cache lines)
#define STR2  272       // c2  row stride (272*8B  = 17 cache lines)
__device__ uint4 g_c01[BB * 260 * STR01];
__device__ uint2 g_c2[BB * 260 * STR2];

__device__ __forceinline__ unsigned packh2(float a, float b) {
    __half2 h = __halves2half2(__float2half(a), __float2half(b));
    return *reinterpret_cast<unsigned*>(&h);
}

__global__ void pack_kernel(const float* __restrict__ x) {
    int ex = blockIdx.x * blockDim.x + threadIdx.x;
    if (ex >= NE) return;
    int ey = blockIdx.y;
    int b = blockIdx.z;
    int x0 = ex - 2, y0 = ey - 2;

    float c[2][2][3];
#pragma unroll
    for (int dy = 0; dy < 2; dy++)
#pragma unroll
        for (int dx = 0; dx < 2; dx++) {
            int yy = y0 + dy, xx = x0 + dx;
            bool v = ((unsigned)yy < (unsigned)HH) && ((unsigned)xx < (unsigned)WW);
            const float* p = x + (size_t)b * CC * HW + yy * WW + xx;
            c[dy][dx][0] = v ? p[0] : 0.0f;
            c[dy][dx][1] = v ? p[HW] : 0.0f;
            c[dy][dx][2] = v ? p[2 * HW] : 0.0f;
        }

    uint4 q;
    q.x = packh2(c[0][0][0], c[0][0][1]);
    q.y = packh2(c[0][1][0], c[0][1][1]);
    q.z = packh2(c[1][0][0], c[1][0][1]);
    q.w = packh2(c[1][1][0], c[1][1][1]);
    g_c01[(b * 260 + ey) * STR01 + ex] = q;

    uint2 r;
    r.x = packh2(c[0][0][2], c[0][1][2]);
    r.y = packh2(c[1][0][2], c[1][1][2]);
    g_c2[(b * 260 + ey) * STR2 + ex] = r;
}

__device__ __forceinline__ void acc01(unsigned h, float w, float& a0, float& a1) {
    __half2 h2 = *reinterpret_cast<const __half2*>(&h);
    float2 f = __half22float2(h2);
    a0 = fmaf(w, f.x, a0);
    a1 = fmaf(w, f.y, a1);
}

// Warp = 4x4 output tile x 2 ky-halves (lane pairs). Block = 8x8 tile.
__global__ void __launch_bounds__(128, 10) stn_kernel(const float* __restrict__ theta,
                                                      float* __restrict__ out) {
    int tid = threadIdx.x;
    int half = tid & 1;
    int p = (tid >> 1) & 15;
    int w = tid >> 5;
    int i = blockIdx.y * 8 + ((w >> 1) << 2) + (p >> 2);
    int j = blockIdx.x * 8 + ((w & 1) << 2) + (p & 3);
    int b = blockIdx.z;
    bool valid = (i < MM) && (j < MM);
    i = min(i, MM - 1);
    j = min(j, MM - 1);

    const float* th = theta + b * 6;
    float t00 = __ldg(th + 0), t01 = __ldg(th + 1), t02 = __ldg(th + 2);
    float t10 = __ldg(th + 3), t11 = __ldg(th + 4), t12 = __ldg(th + 5);

    float lx = (j + 0.5f) * (2.0f / MM) - 1.0f;
    float ly = (i + 0.5f) * (2.0f / MM) - 1.0f;
    float gx = fmaf(t00, lx, fmaf(t01, ly, t02));
    float gy = fmaf(t10, lx, fmaf(t11, ly, t12));

    // pixel-space base, pre-biased by +2 into padded entry index space
    float ixb = fmaf(gx, 0.5f * WW, 0.5f * WW - 0.5f + 2.0f);
    float iyb = fmaf(gy, 0.5f * HH, 0.5f * HH - 0.5f + 2.0f);

    const float cstep = (0.5f * WW) / (6.0f * 99.0f);
    float ux = t00 * cstep, uy = t10 * cstep;
    float vx = t01 * cstep, vy = t11 * cstep;

    // 1D Gaussian blur weights as literals (no register array)
    const float wkx[11] = {0.00386592f, 0.02856550f, 0.13533528f, 0.41111229f,
                           0.80073740f, 1.0f,        0.80073740f, 0.41111229f,
                           0.13533528f, 0.02856550f, 0.00386592f};
    const float wsum = 3.75923278f;
    const float inv = 1.0f / (wsum * wsum);

    const uint4* __restrict__ base01 = g_c01 + b * (260 * STR01);
    const uint2* __restrict__ base2 = g_c2 + b * (260 * STR2);

    float acc0 = 0.0f, acc1 = 0.0f, acc2 = 0.0f;

#pragma unroll 1
    for (int ky = half; ky < 11; ky += 2) {
        float dky = (float)(ky - 5);
        float dd = dky * (1.0f / 6.0f);
        float wyk = expf(-8.0f * dd * dd);
        float ixr = fmaf(dky, vx, ixb);
        float iyr = fmaf(dky, vy, iyb);
#pragma unroll
        for (int kx = 0; kx < 11; kx++) {
            float dkx = (float)(kx - 5);
            float ix = fmaf(dkx, ux, ixr);
            float iy = fmaf(dkx, uy, iyr);

            float x0f = floorf(ix);
            float y0f = floorf(iy);
            float fx = ix - x0f;
            float fy = iy - y0f;
            int xq = min(max((int)x0f, 0), NE - 1);
            int yq = min(max((int)y0f, 0), NR - 1);

            uint4 q = base01[yq * STR01 + xq];
            uint2 r = base2[yq * STR2 + xq];

            float wgt = wyk * wkx[kx];
            float gx0 = 1.0f - fx;
            float a0 = wgt * (1.0f - fy);
            float a1 = wgt * fy;
            float w00 = a0 * gx0, w01 = a0 * fx;
            float w10 = a1 * gx0, w11 = a1 * fx;

            acc01(q.x, w00, acc0, acc1);
            acc01(q.y, w01, acc0, acc1);
            acc01(q.z, w10, acc0, acc1);
            acc01(q.w, w11, acc0, acc1);

            __half2 rlo = *reinterpret_cast<const __half2*>(&r.x);
            __half2 rhi = *reinterpret_cast<const __half2*>(&r.y);
            float2 flo = __half22float2(rlo);
            float2 fhi = __half22float2(rhi);
            acc2 = fmaf(w00, flo.x, acc2);
            acc2 = fmaf(w01, flo.y, acc2);
            acc2 = fmaf(w10, fhi.x, acc2);
            acc2 = fmaf(w11, fhi.y, acc2);
        }
    }

    acc0 += __shfl_xor_sync(0xffffffff, acc0, 1);
    acc1 += __shfl_xor_sync(0xffffffff, acc1, 1);
    acc2 += __shfl_xor_sync(0xffffffff, acc2, 1);

    if (half == 0 && valid) {
        int r = i * MM + j;
        float* ob = out + b * (CC * MM * MM) + r;
        ob[0]           = acc0 * inv;
        ob[MM * MM]     = acc1 * inv;
        ob[2 * MM * MM] = acc2 * inv;
    }
}

extern "C" void kernel_launch(void* const* d_in, const int* in_sizes, int n_in,
                              void* d_out, int out_size) {
    const float* x = (const float*)d_in[0];
    const float* th = (const float*)d_in[1];
    if (n_in >= 2 && in_sizes[0] == 96) {
        x = (const float*)d_in[1];
        th = (const float*)d_in[0];
    }
    float* out = (float*)d_out;

    {
        int tpb = 256;
        dim3 grid((NE + tpb - 1) / tpb, NR, BB);
        pack_kernel<<<grid, tpb>>>(x);
    }
    {
        dim3 grid((MM + 7) / 8, (MM + 7) / 8, BB);
        stn_kernel<<<grid, 128>>>(th, out);
    }
    (void)out_size;
}